// round 16
// baseline (speedup 1.0000x reference)
#include <cuda_runtime.h>
#include <cuda_fp16.h>
#include <cstdint>

#define NROWS  65536
#define DDIM   256
#define KCODES 4096
#define QTZ_BETA 0.25
#define BM 128
#define BNC 256                  // codes per chunk (two half-K stages)
#define NCHUNK (KCODES / BNC)    // 16
#define NSTG (NCHUNK * 2)        // 32 pipeline stages
#define CAP 48

// -------- device scratch --------
__device__ __half g_zh[NROWS][DDIM];    // 32MB (fp16)
__device__ __half g_cbh[KCODES][DDIM];  // 2MB  (fp16)
__device__ float  g_znorm[NROWS];
__device__ float  g_cnorm[KCODES];
__device__ float  g_maxcn;              // grows monotonically; idempotent across replays
__device__ double g_loss;
__device__ int    g_ccount[NROWS];
__device__ int    g_cand[NROWS][CAP];

// -------- smem map (bytes) --------
// A resident (64KB, 512B rows) | B 2 half-K stages (2x64KB, 256B rows) | ctrl | cand
#define OFF_A    0
#define OFF_B    65536
#define BSTG     65536
#define OFF_MIN  (OFF_B + 2 * BSTG)      // 196608 (128 u32)
#define OFF_CNT  (OFF_MIN + 512)
#define OFF_MR   (OFF_CNT + 512)
#define OFF_CAND (OFF_MR + 512)          // 198144: 128*48*4 = 24576
#define SMEM_TOTAL (OFF_CAND + 24576)    // 222720

// ---------------- PTX helpers ----------------
__device__ __forceinline__ uint32_t smem_u32(const void* p) {
    uint32_t a;
    asm("{ .reg .u64 t; cvta.to.shared.u64 t, %1; cvt.u32.u64 %0, t; }" : "=r"(a) : "l"(p));
    return a;
}
__device__ __forceinline__ void cp_async16(uint32_t dst, const void* src) {
    asm volatile("cp.async.cg.shared.global [%0], [%1], 16;" :: "r"(dst), "l"(src) : "memory");
}
#define CP_COMMIT() asm volatile("cp.async.commit_group;" ::: "memory")
#define CP_WAIT(n)  asm volatile("cp.async.wait_group %0;" :: "n"(n) : "memory")

__device__ __forceinline__ void ldsm4(uint32_t* r, uint32_t addr) {
    asm volatile("ldmatrix.sync.aligned.m8n8.x4.shared.b16 {%0,%1,%2,%3}, [%4];"
                 : "=r"(r[0]), "=r"(r[1]), "=r"(r[2]), "=r"(r[3]) : "r"(addr));
}
// fp16 inputs, fp16 accumulate: D/C are 2 regs (4 halves).
// Element map: reg0 = (row, 2c),(row, 2c+1); reg1 = (row+8, 2c),(row+8, 2c+1)
__device__ __forceinline__ void mma_f16acc(uint32_t* c, const uint32_t* a,
                                           uint32_t b0, uint32_t b1) {
    asm volatile(
        "mma.sync.aligned.m16n8k16.row.col.f16.f16.f16.f16 "
        "{%0,%1}, {%2,%3,%4,%5}, {%6,%7}, {%0,%1};"
        : "+r"(c[0]), "+r"(c[1])
        : "r"(a[0]), "r"(a[1]), "r"(a[2]), "r"(a[3]), "r"(b0), "r"(b1));
}

__device__ __forceinline__ uint32_t fkey(float f) {
    uint32_t u = __float_as_uint(f);
    return (u & 0x80000000u) ? ~u : (u | 0x80000000u);
}
__device__ __forceinline__ float funkey(uint32_t k) {
    return __uint_as_float((k & 0x80000000u) ? (k & 0x7fffffffu) : ~k);
}

// ---------------- merged prep: z rows + codebook rows + loss zero ----------------
__device__ __forceinline__ float prep_row(const float* __restrict__ src, int row,
                                          __half (*dst)[DDIM]) {
    int lane = threadIdx.x & 31;
    const float4* zp = (const float4*)(src + (size_t)row * DDIM) + lane * 2;
    float4 a = zp[0], b = zp[1];
    float v[8] = {a.x, a.y, a.z, a.w, b.x, b.y, b.z, b.w};
    float ns = 0.f;
    uint32_t p[4];
    #pragma unroll
    for (int j = 0; j < 4; j++) {
        float x0 = v[2 * j], x1 = v[2 * j + 1];
        ns += x0 * x0 + x1 * x1;
        __half2 h2 = __floats2half2_rn(x0, x1);
        p[j] = *reinterpret_cast<uint32_t*>(&h2);
    }
    ((uint4*)dst[row])[lane] = make_uint4(p[0], p[1], p[2], p[3]);
    #pragma unroll
    for (int o = 16; o > 0; o >>= 1) ns += __shfl_down_sync(0xffffffffu, ns, o);
    return ns;
}

#define PREPZ_BLOCKS (NROWS / 8)     // 8192
#define PREP_BLOCKS  (PREPZ_BLOCKS + KCODES / 8)   // 8704

__global__ void prep_all(const float* __restrict__ z, const float* __restrict__ cb) {
    if (blockIdx.x < PREPZ_BLOCKS) {
        int row = blockIdx.x * 8 + (threadIdx.x >> 5);
        float ns = prep_row(z, row, g_zh);
        if ((threadIdx.x & 31) == 0) g_znorm[row] = ns;
    } else {
        int row = (blockIdx.x - PREPZ_BLOCKS) * 8 + (threadIdx.x >> 5);
        float ns = prep_row(cb, row, g_cbh);
        if ((threadIdx.x & 31) == 0) {
            g_cnorm[row] = ns;
            atomicMax((int*)&g_maxcn, __float_as_int(ns));
            if (row == 0) g_loss = 0.0;   // rescore (later kernel) is the only writer
        }
    }
}

// ---------------- loaders (512 threads) ----------------
// A rows are 512B (K=256); swizzle 16B-chunk c (0..31) with row&7
__device__ __forceinline__ void load_A(uint32_t sb, int rowBase, int tid) {
    #pragma unroll
    for (int j = 0; j < 8; j++) {
        const int q = j * 512 + tid;    // 0..4095
        const int r = q >> 5, c = q & 31;
        cp_async16(sb + OFF_A + r * 512 + ((c ^ (r & 7)) << 4),
                   &g_zh[rowBase + r][c * 8]);
    }
}
// B stage s: chunk s>>1, K-half s&1; rows are 256B (128 k)
__device__ __forceinline__ void load_B(uint32_t sb, int s, int tid) {
    const uint32_t dst = sb + OFF_B + (uint32_t)(s & 1) * BSTG;
    const int codeBase = (s >> 1) * BNC;
    const int dOff = (s & 1) * 128;
    #pragma unroll
    for (int j = 0; j < 8; j++) {
        const int q = j * 512 + tid;    // 0..4095
        const int r = q >> 4, c = q & 15;
        cp_async16(dst + r * 256 + ((c ^ (r & 7)) << 4),
                   &g_cbh[codeBase + r][dOff + c * 8]);
    }
}

// ---------------- pass1: approx GEMM (fp16 accum) + candidates ----------------
// 16 warps, warp tile 32 rows x 64 codes (mW 4-way, nW 4-way over 128x256),
// A resident full-K, B half-K 2-stage; epilogue per 256-code chunk.
__global__ __launch_bounds__(512, 1)
void vq_approx() {
    extern __shared__ char smem[];
    const uint32_t sb = smem_u32(smem);
    const int tid = threadIdx.x;
    const uint32_t lane = tid & 31;
    const int wid = tid >> 5;
    const int mW = wid & 3;        // 4-way M (32 rows)
    const int nW = wid >> 2;       // 4-way N (64 codes)
    const int rowBase = blockIdx.x * BM;

    uint32_t* sMin  = (uint32_t*)(smem + OFF_MIN);
    int*      sCnt  = (int*)(smem + OFF_CNT);
    float*    sMr   = (float*)(smem + OFF_MR);
    int*      sCand = (int*)(smem + OFF_CAND);

    if (tid < BM) {
        sMin[tid] = 0xFFFFFFFFu;
        sCnt[tid] = 0;
        // fp16 input rounding (2^-10 |z||c|) + fp16 accumulation (~0.8 worst)
        sMr[tid]  = 0.02f * sqrtf(g_znorm[rowBase + tid]) * sqrtf(g_maxcn) + 1.0f;
    }

    const uint32_t rowAoff = ((uint32_t)(mW * 32) + (lane & 15)) * 512;
    const uint32_t nRowoff = ((uint32_t)(nW * 64) + (lane & 7) + ((lane >> 4) << 3)) * 256;
    const uint32_t swz = lane & 7;
    const uint32_t kHA = lane >> 4;
    const uint32_t kHB = (lane >> 3) & 1;

    uint32_t acc[2][8][2];
    #pragma unroll
    for (int mt = 0; mt < 2; mt++)
        #pragma unroll
        for (int nt = 0; nt < 8; nt++) { acc[mt][nt][0] = 0u; acc[mt][nt][1] = 0u; }

    // prologue: A (resident) + stage 0, single group
    load_A(sb, rowBase, tid);
    load_B(sb, 0, tid);
    CP_COMMIT();

    #pragma unroll 1
    for (int s = 0; s < NSTG; s++) {
        CP_WAIT(0);                 // my copies for stage s complete...
        __syncthreads();            // ...visible to all; retires reads of s-1
        if (s + 1 < NSTG) load_B(sb, s + 1, tid);
        CP_COMMIT();

        const uint32_t aB = sb + OFF_A + rowAoff;
        const uint32_t bB = sb + OFF_B + (uint32_t)(s & 1) * BSTG + nRowoff;
        const uint32_t akBase = (uint32_t)(s & 1) * 8;   // A k-step offset

        #pragma unroll
        for (int kk = 0; kk < 8; kk++) {
            const uint32_t aCol = ((2u * (akBase + kk) + kHA) ^ swz) << 4;
            const uint32_t bCol = ((2u * kk + kHB) ^ swz) << 4;
            uint32_t a[2][4], b[4][4];
            ldsm4(a[0], aB + 0 * 8192 + aCol);
            ldsm4(a[1], aB + 1 * 8192 + aCol);
            ldsm4(b[0], bB + 0 * 4096 + bCol);
            ldsm4(b[1], bB + 1 * 4096 + bCol);
            ldsm4(b[2], bB + 2 * 4096 + bCol);
            ldsm4(b[3], bB + 3 * 4096 + bCol);
            #pragma unroll
            for (int mt = 0; mt < 2; mt++)
                #pragma unroll
                for (int i = 0; i < 4; i++) {
                    mma_f16acc(acc[mt][2 * i],     a[mt], b[i][0], b[i][1]);
                    mma_f16acc(acc[mt][2 * i + 1], a[mt], b[i][2], b[i][3]);
                }
        }

        if (s & 1) {
            // ---- chunk epilogue (per 256 codes): e = ||c||^2 - 2 z.c ----
            const int jb = (s >> 1) * BNC + nW * 64 + (int)(lane & 3) * 2;

            float rmin[4];
            #pragma unroll
            for (int q = 0; q < 4; q++) rmin[q] = 3.4e38f;

            #pragma unroll
            for (int nt = 0; nt < 8; nt++) {
                const float2 cn = __ldg((const float2*)(g_cnorm + jb + nt * 8));
                #pragma unroll
                for (int mt = 0; mt < 2; mt++) {
                    const float2 vlo = __half22float2(*(const __half2*)&acc[mt][nt][0]);
                    const float2 vhi = __half22float2(*(const __half2*)&acc[mt][nt][1]);
                    float e0 = fmaf(-2.f, vlo.x, cn.x);
                    float e1 = fmaf(-2.f, vlo.y, cn.y);
                    float e2 = fmaf(-2.f, vhi.x, cn.x);
                    float e3 = fmaf(-2.f, vhi.y, cn.y);
                    rmin[2 * mt]     = fminf(rmin[2 * mt],     fminf(e0, e1));
                    rmin[2 * mt + 1] = fminf(rmin[2 * mt + 1], fminf(e2, e3));
                }
            }
            #pragma unroll
            for (int q = 0; q < 4; q++) {
                rmin[q] = fminf(rmin[q], __shfl_xor_sync(0xffffffffu, rmin[q], 1));
                rmin[q] = fminf(rmin[q], __shfl_xor_sync(0xffffffffu, rmin[q], 2));
            }
            #pragma unroll
            for (int q = 0; q < 4; q++) {
                const int mt = q >> 1, h = q & 1;
                const int r = mW * 32 + mt * 16 + (int)(lane >> 2) + h * 8;
                if ((lane & 3) == 0) atomicMin(&sMin[r], fkey(rmin[q]));
                const float th = fminf(funkey(sMin[r]), rmin[q]) + sMr[r];
                #pragma unroll
                for (int nt = 0; nt < 8; nt++) {
                    const float2 cn = __ldg((const float2*)(g_cnorm + jb + nt * 8));
                    const float2 vv = __half22float2(*(const __half2*)&acc[mt][nt][h]);
                    const float ev0 = fmaf(-2.f, vv.x, cn.x);
                    const float ev1 = fmaf(-2.f, vv.y, cn.y);
                    if (ev0 <= th) {
                        int p = atomicAdd(&sCnt[r], 1);
                        if (p < CAP) sCand[r * CAP + p] = jb + nt * 8;
                    }
                    if (ev1 <= th) {
                        int p = atomicAdd(&sCnt[r], 1);
                        if (p < CAP) sCand[r * CAP + p] = jb + nt * 8 + 1;
                    }
                }
            }
            #pragma unroll
            for (int mt = 0; mt < 2; mt++)
                #pragma unroll
                for (int nt = 0; nt < 8; nt++) { acc[mt][nt][0] = 0u; acc[mt][nt][1] = 0u; }
        }
    }

    __syncthreads();
    if (tid < BM) {
        const int cnt = sCnt[tid];
        g_ccount[rowBase + tid] = cnt;
        const int m = cnt < CAP ? cnt : CAP;
        for (int i = 0; i < m; i++)
            g_cand[rowBase + tid][i] = sCand[tid * CAP + i];
    }
}

// ---------------- pass2: exact fp32 rescore + outputs ----------------
__device__ __forceinline__ float cand_dot(const float4& za, const float4& zb,
                                          const float* __restrict__ cb, int id,
                                          int lane) {
    const float4* cp = (const float4*)(cb + (size_t)id * DDIM);
    float4 ca = cp[lane * 2], cc = cp[lane * 2 + 1];
    float d = za.x * ca.x;
    d = fmaf(za.y, ca.y, d); d = fmaf(za.z, ca.z, d); d = fmaf(za.w, ca.w, d);
    d = fmaf(zb.x, cc.x, d); d = fmaf(zb.y, cc.y, d);
    d = fmaf(zb.z, cc.z, d); d = fmaf(zb.w, cc.w, d);
    return d;
}

__global__ __launch_bounds__(256, 1)
void vq_rescore(const float* __restrict__ z, const float* __restrict__ cb,
                float* __restrict__ zq, float* __restrict__ ids_out) {
    __shared__ float sL[8];
    const int w = threadIdx.x >> 5, lane = threadIdx.x & 31;
    const int row = blockIdx.x * 8 + w;

    const float4* zp = (const float4*)(z + (size_t)row * DDIM);
    const float4 za = zp[lane * 2], zb = zp[lane * 2 + 1];
    const float zn = g_znorm[row];
    const int n = g_ccount[row];

    float best = 3.4e38f;
    int bid = 0x7fffffff;
    if (n <= CAP) {
        int i = 0;
        // 2-way unrolled: two concurrent codebook-row loads for MLP
        for (; i + 1 < n; i += 2) {
            const int id0 = g_cand[row][i];
            const int id1 = g_cand[row][i + 1];
            float d0 = cand_dot(za, zb, cb, id0, lane);
            float d1 = cand_dot(za, zb, cb, id1, lane);
            #pragma unroll
            for (int o = 16; o > 0; o >>= 1) {
                d0 += __shfl_xor_sync(0xffffffffu, d0, o);
                d1 += __shfl_xor_sync(0xffffffffu, d1, o);
            }
            float e0 = zn - 2.f * d0 + g_cnorm[id0];
            float e1 = zn - 2.f * d1 + g_cnorm[id1];
            if (e0 < best || (e0 == best && id0 < bid)) { best = e0; bid = id0; }
            if (e1 < best || (e1 == best && id1 < bid)) { best = e1; bid = id1; }
        }
        if (i < n) {
            const int id0 = g_cand[row][i];
            float d0 = cand_dot(za, zb, cb, id0, lane);
            #pragma unroll
            for (int o = 16; o > 0; o >>= 1) d0 += __shfl_xor_sync(0xffffffffu, d0, o);
            float e0 = zn - 2.f * d0 + g_cnorm[id0];
            if (e0 < best || (e0 == best && id0 < bid)) { best = e0; bid = id0; }
        }
    } else {
        for (int id = 0; id < KCODES; id++) {
            float d = cand_dot(za, zb, cb, id, lane);
            #pragma unroll
            for (int o = 16; o > 0; o >>= 1) d += __shfl_xor_sync(0xffffffffu, d, o);
            float e = zn - 2.f * d + g_cnorm[id];
            if (e < best || (e == best && id < bid)) { best = e; bid = id; }
        }
    }

    ids_out[row] = (float)bid;
    const float4* cp = (const float4*)(cb + (size_t)bid * DDIM);
    float4* dst = (float4*)(zq + (size_t)row * DDIM);
    dst[lane * 2]     = cp[lane * 2];
    dst[lane * 2 + 1] = cp[lane * 2 + 1];

    if (lane == 0) sL[w] = best;
    __syncthreads();
    if (threadIdx.x == 0) {
        float s = 0.f;
        #pragma unroll
        for (int i = 0; i < 8; i++) s += sL[i];
        atomicAdd(&g_loss, (double)s);
    }
}

// ---------------- loss finalize ----------------
__global__ void finalize_kernel(float* __restrict__ loss_out) {
    *loss_out = (float)(g_loss * (1.0 + QTZ_BETA) / ((double)NROWS * (double)DDIM));
}

// ---------------- launch ----------------
extern "C" void kernel_launch(void* const* d_in, const int* in_sizes, int n_in,
                              void* d_out, int out_size) {
    const float* z  = (const float*)d_in[0];
    const float* cb = (const float*)d_in[1];
    float* out = (float*)d_out;

    float* zq_out   = out;                          // N*D
    float* loss_out = out + (size_t)NROWS * DDIM;   // 1
    float* ids_out  = loss_out + 1;                 // N

    cudaFuncSetAttribute(vq_approx, cudaFuncAttributeMaxDynamicSharedMemorySize, SMEM_TOTAL);

    prep_all<<<PREP_BLOCKS, 256>>>(z, cb);
    vq_approx<<<NROWS / BM, 512, SMEM_TOTAL>>>();
    vq_rescore<<<NROWS / 8, 256>>>(z, cb, zq_out, ids_out);
    finalize_kernel<<<1, 1>>>(loss_out);
}

// round 17
// speedup vs baseline: 1.1012x; 1.1012x over previous
#include <cuda_runtime.h>
#include <cuda_bf16.h>
#include <cstdint>

#define NROWS  65536
#define DDIM   256
#define KCODES 4096
#define QTZ_BETA 0.25
#define BM 128
#define KSPLIT 2
#define CODES_PER_CTA (KCODES / KSPLIT)  // 2048
#define BNC 256                  // codes per chunk (two half-K stages)
#define NCHUNK (CODES_PER_CTA / BNC)     // 8
#define NSTG (NCHUNK * 2)        // 16 pipeline stages
#define CAP 48

// -------- device scratch --------
__device__ __nv_bfloat16 g_zh[NROWS][DDIM];    // 32MB
__device__ __nv_bfloat16 g_cbh[KCODES][DDIM];  // 2MB
__device__ float  g_znorm[NROWS];
__device__ float  g_cnorm[KCODES];
__device__ float  g_maxcn;                     // monotone; idempotent across replays
__device__ double g_loss;
__device__ int    g_ccount[NROWS];
__device__ int    g_cand[NROWS][CAP];

// -------- smem map (bytes) --------
// A resident (64KB, 512B rows) | B 2 half-K stages (2x64KB, 256B rows) | ctrl | cand
#define OFF_A    0
#define OFF_B    65536
#define BSTG     65536
#define OFF_MIN  (OFF_B + 2 * BSTG)      // 196608 (128 u32)
#define OFF_CNT  (OFF_MIN + 512)
#define OFF_MR   (OFF_CNT + 512)
#define OFF_CAND (OFF_MR + 512)          // 198144: 128*48*4 = 24576
#define SMEM_TOTAL (OFF_CAND + 24576)    // 222720

// ---------------- PTX helpers ----------------
__device__ __forceinline__ uint32_t smem_u32(const void* p) {
    uint32_t a;
    asm("{ .reg .u64 t; cvta.to.shared.u64 t, %1; cvt.u32.u64 %0, t; }" : "=r"(a) : "l"(p));
    return a;
}
__device__ __forceinline__ void cp_async16(uint32_t dst, const void* src) {
    asm volatile("cp.async.cg.shared.global [%0], [%1], 16;" :: "r"(dst), "l"(src) : "memory");
}
#define CP_COMMIT() asm volatile("cp.async.commit_group;" ::: "memory")
#define CP_WAIT(n)  asm volatile("cp.async.wait_group %0;" :: "n"(n) : "memory")

__device__ __forceinline__ void ldsm4(uint32_t* r, uint32_t addr) {
    asm volatile("ldmatrix.sync.aligned.m8n8.x4.shared.b16 {%0,%1,%2,%3}, [%4];"
                 : "=r"(r[0]), "=r"(r[1]), "=r"(r[2]), "=r"(r[3]) : "r"(addr));
}
__device__ __forceinline__ void mma_bf16(float* c, const uint32_t* a,
                                         uint32_t b0, uint32_t b1) {
    asm volatile(
        "mma.sync.aligned.m16n8k16.row.col.f32.bf16.bf16.f32 "
        "{%0,%1,%2,%3}, {%4,%5,%6,%7}, {%8,%9}, {%0,%1,%2,%3};"
        : "+f"(c[0]), "+f"(c[1]), "+f"(c[2]), "+f"(c[3])
        : "r"(a[0]), "r"(a[1]), "r"(a[2]), "r"(a[3]), "r"(b0), "r"(b1));
}

__device__ __forceinline__ uint32_t fkey(float f) {
    uint32_t u = __float_as_uint(f);
    return (u & 0x80000000u) ? ~u : (u | 0x80000000u);
}
__device__ __forceinline__ float funkey(uint32_t k) {
    return __uint_as_float((k & 0x80000000u) ? (k & 0x7fffffffu) : ~k);
}

// ---------------- merged prep: z rows + codebook rows + resets ----------------
__device__ __forceinline__ float prep_row(const float* __restrict__ src, int row,
                                          __nv_bfloat16 (*dst)[DDIM]) {
    int lane = threadIdx.x & 31;
    const float4* zp = (const float4*)(src + (size_t)row * DDIM) + lane * 2;
    float4 a = zp[0], b = zp[1];
    float v[8] = {a.x, a.y, a.z, a.w, b.x, b.y, b.z, b.w};
    float ns = 0.f;
    uint32_t p[4];
    #pragma unroll
    for (int j = 0; j < 4; j++) {
        float x0 = v[2 * j], x1 = v[2 * j + 1];
        ns += x0 * x0 + x1 * x1;
        __nv_bfloat162 h2 = __float22bfloat162_rn(make_float2(x0, x1));
        p[j] = *reinterpret_cast<uint32_t*>(&h2);
    }
    ((uint4*)dst[row])[lane] = make_uint4(p[0], p[1], p[2], p[3]);
    #pragma unroll
    for (int o = 16; o > 0; o >>= 1) ns += __shfl_down_sync(0xffffffffu, ns, o);
    return ns;
}

#define PREPZ_BLOCKS (NROWS / 8)     // 8192
#define PREP_BLOCKS  (PREPZ_BLOCKS + KCODES / 8)   // 8704

__global__ void prep_all(const float* __restrict__ z, const float* __restrict__ cb) {
    if (blockIdx.x < PREPZ_BLOCKS) {
        int row = blockIdx.x * 8 + (threadIdx.x >> 5);
        float ns = prep_row(z, row, g_zh);
        if ((threadIdx.x & 31) == 0) {
            g_znorm[row] = ns;
            g_ccount[row] = 0;            // candidate lists reset each replay
        }
    } else {
        int row = (blockIdx.x - PREPZ_BLOCKS) * 8 + (threadIdx.x >> 5);
        float ns = prep_row(cb, row, g_cbh);
        if ((threadIdx.x & 31) == 0) {
            g_cnorm[row] = ns;
            atomicMax((int*)&g_maxcn, __float_as_int(ns));
            if (row == 0) g_loss = 0.0;   // rescore (later kernel) is the only writer
        }
    }
}

// ---------------- loaders (512 threads) ----------------
// A rows are 512B (K=256); swizzle 16B-chunk c (0..31) with row&7
__device__ __forceinline__ void load_A(uint32_t sb, int rowBase, int tid) {
    #pragma unroll
    for (int j = 0; j < 8; j++) {
        const int q = j * 512 + tid;    // 0..4095
        const int r = q >> 5, c = q & 31;
        cp_async16(sb + OFF_A + r * 512 + ((c ^ (r & 7)) << 4),
                   &g_zh[rowBase + r][c * 8]);
    }
}
// B stage s: chunk s>>1 within this CTA's code half, K-half s&1; rows are 256B
__device__ __forceinline__ void load_B(uint32_t sb, int codeHalfBase, int s, int tid) {
    const uint32_t dst = sb + OFF_B + (uint32_t)(s & 1) * BSTG;
    const int codeBase = codeHalfBase + (s >> 1) * BNC;
    const int dOff = (s & 1) * 128;
    #pragma unroll
    for (int j = 0; j < 8; j++) {
        const int q = j * 512 + tid;    // 0..4095
        const int r = q >> 4, c = q & 15;
        cp_async16(dst + r * 256 + ((c ^ (r & 7)) << 4),
                   &g_cbh[codeBase + r][dOff + c * 8]);
    }
}

// ---------------- pass1: approx GEMM + candidate collection ----------------
// Grid = (NROWS/BM) * KSPLIT: CTA handles 128 rows x 2048 codes.
// 16 warps, warp tile 32 rows x 64 codes; A resident, B half-K 2-stage.
__global__ __launch_bounds__(512, 1)
void vq_approx() {
    extern __shared__ char smem[];
    const uint32_t sb = smem_u32(smem);
    const int tid = threadIdx.x;
    const uint32_t lane = tid & 31;
    const int wid = tid >> 5;
    const int mW = wid & 3;        // 4-way M (32 rows)
    const int nW = wid >> 2;       // 4-way N (64 codes)
    const int rowBase = (blockIdx.x >> 1) * BM;
    const int codeHalfBase = (blockIdx.x & 1) * CODES_PER_CTA;

    uint32_t* sMin  = (uint32_t*)(smem + OFF_MIN);
    int*      sCnt  = (int*)(smem + OFF_CNT);
    float*    sMr   = (float*)(smem + OFF_MR);
    int*      sCand = (int*)(smem + OFF_CAND);

    if (tid < BM) {
        sMin[tid] = 0xFFFFFFFFu;
        sCnt[tid] = 0;
        // rigorous bf16-RN bound 2^-7 |z||c| (=0.0078 coeff) + slack
        sMr[tid]  = 0.0098f * sqrtf(g_znorm[rowBase + tid]) * sqrtf(g_maxcn) + 0.1f;
    }

    const uint32_t rowAoff = ((uint32_t)(mW * 32) + (lane & 15)) * 512;
    const uint32_t nRowoff = ((uint32_t)(nW * 64) + (lane & 7) + ((lane >> 4) << 3)) * 256;
    const uint32_t swz = lane & 7;
    const uint32_t kHA = lane >> 4;
    const uint32_t kHB = (lane >> 3) & 1;

    float acc[2][8][4];
    #pragma unroll
    for (int mt = 0; mt < 2; mt++)
        #pragma unroll
        for (int nt = 0; nt < 8; nt++)
            #pragma unroll
            for (int e = 0; e < 4; e++) acc[mt][nt][e] = 0.f;

    // prologue: A (resident) + stage 0, single group
    load_A(sb, rowBase, tid);
    load_B(sb, codeHalfBase, 0, tid);
    CP_COMMIT();

    #pragma unroll 1
    for (int s = 0; s < NSTG; s++) {
        CP_WAIT(0);                 // my copies for stage s complete...
        __syncthreads();            // ...visible to all; retires reads of s-1
        if (s + 1 < NSTG) load_B(sb, codeHalfBase, s + 1, tid);
        CP_COMMIT();

        const uint32_t aB = sb + OFF_A + rowAoff;
        const uint32_t bB = sb + OFF_B + (uint32_t)(s & 1) * BSTG + nRowoff;
        const uint32_t akBase = (uint32_t)(s & 1) * 8;   // A k-step offset

        #pragma unroll
        for (int kk = 0; kk < 8; kk++) {
            const uint32_t aCol = ((2u * (akBase + kk) + kHA) ^ swz) << 4;
            const uint32_t bCol = ((2u * kk + kHB) ^ swz) << 4;
            uint32_t a[2][4], b[4][4];
            ldsm4(a[0], aB + 0 * 8192 + aCol);
            ldsm4(a[1], aB + 1 * 8192 + aCol);
            ldsm4(b[0], bB + 0 * 4096 + bCol);
            ldsm4(b[1], bB + 1 * 4096 + bCol);
            ldsm4(b[2], bB + 2 * 4096 + bCol);
            ldsm4(b[3], bB + 3 * 4096 + bCol);
            #pragma unroll
            for (int mt = 0; mt < 2; mt++)
                #pragma unroll
                for (int i = 0; i < 4; i++) {
                    mma_bf16(acc[mt][2 * i],     a[mt], b[i][0], b[i][1]);
                    mma_bf16(acc[mt][2 * i + 1], a[mt], b[i][2], b[i][3]);
                }
        }

        if (s & 1) {
            // ---- chunk epilogue (per 256 codes): e = ||c||^2 - 2 z.c ----
            const int jb = codeHalfBase + (s >> 1) * BNC + nW * 64 + (int)(lane & 3) * 2;

            float rmin[4];
            #pragma unroll
            for (int q = 0; q < 4; q++) rmin[q] = 3.4e38f;

            #pragma unroll
            for (int nt = 0; nt < 8; nt++) {
                const float2 cn = __ldg((const float2*)(g_cnorm + jb + nt * 8));
                #pragma unroll
                for (int mt = 0; mt < 2; mt++) {
                    float e0 = fmaf(-2.f, acc[mt][nt][0], cn.x);
                    float e1 = fmaf(-2.f, acc[mt][nt][1], cn.y);
                    float e2 = fmaf(-2.f, acc[mt][nt][2], cn.x);
                    float e3 = fmaf(-2.f, acc[mt][nt][3], cn.y);
                    acc[mt][nt][0] = e0; acc[mt][nt][1] = e1;
                    acc[mt][nt][2] = e2; acc[mt][nt][3] = e3;
                    rmin[2 * mt]     = fminf(rmin[2 * mt],     fminf(e0, e1));
                    rmin[2 * mt + 1] = fminf(rmin[2 * mt + 1], fminf(e2, e3));
                }
            }
            #pragma unroll
            for (int q = 0; q < 4; q++) {
                rmin[q] = fminf(rmin[q], __shfl_xor_sync(0xffffffffu, rmin[q], 1));
                rmin[q] = fminf(rmin[q], __shfl_xor_sync(0xffffffffu, rmin[q], 2));
            }
            #pragma unroll
            for (int q = 0; q < 4; q++) {
                const int mt = q >> 1, h = q & 1;
                const int r = mW * 32 + mt * 16 + (int)(lane >> 2) + h * 8;
                if ((lane & 3) == 0) atomicMin(&sMin[r], fkey(rmin[q]));
                // subset-min + margin still upper-bounds the true argmin's e
                const float th = fminf(funkey(sMin[r]), rmin[q]) + sMr[r];
                #pragma unroll
                for (int nt = 0; nt < 8; nt++) {
                    const float ev0 = acc[mt][nt][2 * h];
                    const float ev1 = acc[mt][nt][2 * h + 1];
                    if (ev0 <= th) {
                        int p = atomicAdd(&sCnt[r], 1);
                        if (p < CAP) sCand[r * CAP + p] = jb + nt * 8;
                    }
                    if (ev1 <= th) {
                        int p = atomicAdd(&sCnt[r], 1);
                        if (p < CAP) sCand[r * CAP + p] = jb + nt * 8 + 1;
                    }
                }
            }
            #pragma unroll
            for (int mt = 0; mt < 2; mt++)
                #pragma unroll
                for (int nt = 0; nt < 8; nt++) {
                    acc[mt][nt][0] = 0.f; acc[mt][nt][1] = 0.f;
                    acc[mt][nt][2] = 0.f; acc[mt][nt][3] = 0.f;
                }
        }
    }

    __syncthreads();
    // flush: merge this CTA's per-row lists into the global list via atomic base
    if (tid < BM) {
        const int row = rowBase + tid;
        const int cnt = sCnt[tid];
        if (cnt > 0) {
            const int base = atomicAdd(&g_ccount[row], cnt);
            const int m = cnt < CAP ? cnt : CAP;
            for (int i = 0; i < m && base + i < CAP; i++)
                g_cand[row][base + i] = sCand[tid * CAP + i];
        }
    }
}

// ---------------- pass2: exact fp32 rescore + outputs ----------------
__device__ __forceinline__ float cand_dot(const float4& za, const float4& zb,
                                          const float* __restrict__ cb, int id,
                                          int lane) {
    const float4* cp = (const float4*)(cb + (size_t)id * DDIM);
    float4 ca = cp[lane * 2], cc = cp[lane * 2 + 1];
    float d = za.x * ca.x;
    d = fmaf(za.y, ca.y, d); d = fmaf(za.z, ca.z, d); d = fmaf(za.w, ca.w, d);
    d = fmaf(zb.x, cc.x, d); d = fmaf(zb.y, cc.y, d);
    d = fmaf(zb.z, cc.z, d); d = fmaf(zb.w, cc.w, d);
    return d;
}

__global__ __launch_bounds__(256, 1)
void vq_rescore(const float* __restrict__ z, const float* __restrict__ cb,
                float* __restrict__ zq, float* __restrict__ ids_out) {
    __shared__ float sL[8];
    const int w = threadIdx.x >> 5, lane = threadIdx.x & 31;
    const int row = blockIdx.x * 8 + w;

    const float4* zp = (const float4*)(z + (size_t)row * DDIM);
    const float4 za = zp[lane * 2], zb = zp[lane * 2 + 1];
    const float zn = g_znorm[row];
    const int n = g_ccount[row];

    float best = 3.4e38f;
    int bid = 0x7fffffff;
    if (n <= CAP) {
        int i = 0;
        // 2-way unrolled: two concurrent codebook-row loads for MLP
        for (; i + 1 < n; i += 2) {
            const int id0 = g_cand[row][i];
            const int id1 = g_cand[row][i + 1];
            float d0 = cand_dot(za, zb, cb, id0, lane);
            float d1 = cand_dot(za, zb, cb, id1, lane);
            #pragma unroll
            for (int o = 16; o > 0; o >>= 1) {
                d0 += __shfl_xor_sync(0xffffffffu, d0, o);
                d1 += __shfl_xor_sync(0xffffffffu, d1, o);
            }
            float e0 = zn - 2.f * d0 + g_cnorm[id0];
            float e1 = zn - 2.f * d1 + g_cnorm[id1];
            if (e0 < best || (e0 == best && id0 < bid)) { best = e0; bid = id0; }
            if (e1 < best || (e1 == best && id1 < bid)) { best = e1; bid = id1; }
        }
        if (i < n) {
            const int id0 = g_cand[row][i];
            float d0 = cand_dot(za, zb, cb, id0, lane);
            #pragma unroll
            for (int o = 16; o > 0; o >>= 1) d0 += __shfl_xor_sync(0xffffffffu, d0, o);
            float e0 = zn - 2.f * d0 + g_cnorm[id0];
            if (e0 < best || (e0 == best && id0 < bid)) { best = e0; bid = id0; }
        }
    } else {
        for (int id = 0; id < KCODES; id++) {
            float d = cand_dot(za, zb, cb, id, lane);
            #pragma unroll
            for (int o = 16; o > 0; o >>= 1) d += __shfl_xor_sync(0xffffffffu, d, o);
            float e = zn - 2.f * d + g_cnorm[id];
            if (e < best || (e == best && id < bid)) { best = e; bid = id; }
        }
    }

    ids_out[row] = (float)bid;
    const float4* cp = (const float4*)(cb + (size_t)bid * DDIM);
    float4* dst = (float4*)(zq + (size_t)row * DDIM);
    dst[lane * 2]     = cp[lane * 2];
    dst[lane * 2 + 1] = cp[lane * 2 + 1];

    if (lane == 0) sL[w] = best;
    __syncthreads();
    if (threadIdx.x == 0) {
        float s = 0.f;
        #pragma unroll
        for (int i = 0; i < 8; i++) s += sL[i];
        atomicAdd(&g_loss, (double)s);
    }
}

// ---------------- loss finalize ----------------
__global__ void finalize_kernel(float* __restrict__ loss_out) {
    *loss_out = (float)(g_loss * (1.0 + QTZ_BETA) / ((double)NROWS * (double)DDIM));
}

// ---------------- launch ----------------
extern "C" void kernel_launch(void* const* d_in, const int* in_sizes, int n_in,
                              void* d_out, int out_size) {
    const float* z  = (const float*)d_in[0];
    const float* cb = (const float*)d_in[1];
    float* out = (float*)d_out;

    float* zq_out   = out;                          // N*D
    float* loss_out = out + (size_t)NROWS * DDIM;   // 1
    float* ids_out  = loss_out + 1;                 // N

    cudaFuncSetAttribute(vq_approx, cudaFuncAttributeMaxDynamicSharedMemorySize, SMEM_TOTAL);

    prep_all<<<PREP_BLOCKS, 256>>>(z, cb);
    vq_approx<<<(NROWS / BM) * KSPLIT, 512, SMEM_TOTAL>>>();
    vq_rescore<<<NROWS / 8, 256>>>(z, cb, zq_out, ids_out);
    finalize_kernel<<<1, 1>>>(loss_out);
}